// round 9
// baseline (speedup 1.0000x reference)
#include <cuda_runtime.h>
#include <math.h>
#include <stdint.h>

#define B_ 2
#define S_ 2048
#define D_ 1024
#define H_ 16
#define M_ (B_*S_)

// Scratch (allocation-free rule: __device__ globals)
__device__ float g_Qp[(size_t)B_*S_*D_];
__device__ float g_Kp[(size_t)B_*S_*D_];
__device__ float g_Vp[(size_t)B_*S_*D_];
__device__ float g_Att[(size_t)B_*S_*D_];

__device__ __forceinline__ uint32_t f2tf32(float x) {
    uint32_t r;
    asm("cvt.rna.tf32.f32 %0, %1;" : "=r"(r) : "f"(x));
    return r;
}

__device__ __forceinline__ void mma_tf32(float* d, const uint32_t* a, const uint32_t* b) {
    asm volatile(
        "mma.sync.aligned.m16n8k8.row.col.f32.tf32.tf32.f32 "
        "{%0,%1,%2,%3}, {%4,%5,%6,%7}, {%8,%9}, {%0,%1,%2,%3};"
        : "+f"(d[0]), "+f"(d[1]), "+f"(d[2]), "+f"(d[3])
        : "r"(a[0]), "r"(a[1]), "r"(a[2]), "r"(a[3]), "r"(b[0]), "r"(b[1]));
}

__device__ __forceinline__ uint32_t smem_u32(const void* p) {
    uint32_t a;
    asm("{ .reg .u64 t; cvta.to.shared.u64 t, %1; cvt.u32.u64 %0, t; }"
        : "=r"(a) : "l"(p));
    return a;
}

__device__ __forceinline__ void cp_async16(uint32_t saddr, const void* g) {
    asm volatile("cp.async.cg.shared.global [%0], [%1], 16;"
                 :: "r"(saddr), "l"(g) : "memory");
}
#define CP_COMMIT()  asm volatile("cp.async.commit_group;" ::: "memory")
#define CP_WAIT(n_)  asm volatile("cp.async.wait_group %0;" :: "n"(n_) : "memory")

// ---------------------------------------------------------------------------
// tf32 mma.sync GEMM (round-6 2-stage version, measured 198.9us on qkv)
// ---------------------------------------------------------------------------
#define GST_ 36
#define GSTAGE_ (128*GST_)

template<int DO_ROPE>
__device__ __forceinline__ void gemm_mma_body(const float* __restrict__ A,
                                              const float* __restrict__ W,
                                              const float* __restrict__ bias,
                                              float* __restrict__ C)
{
    extern __shared__ float gsm_[];
    float* Asf = gsm_;                    // [2][128][36]
    float* Bsf = gsm_ + 2 * GSTAGE_;      // [2][128][36]

    const int tid  = threadIdx.x;
    const int lane = tid & 31, w = tid >> 5;
    const int warpM = w & 1, warpN = w >> 1;
    const int g = lane >> 2, tg = lane & 3;
    const int m0 = blockIdx.y * 128, n0 = blockIdx.x * 128;

    const uint32_t sA_u = smem_u32(Asf);
    const uint32_t sB_u = smem_u32(Bsf);

    #define ISSUE_STAGE(s_, buf_) do {                                        \
        const int k0_ = (s_) * 32;                                            \
        _Pragma("unroll")                                                     \
        for (int t = 0; t < 4; t++) {                                         \
            int slot = tid + t * 256;                                         \
            int r = slot >> 3, qd = slot & 7;                                 \
            uint32_t so = (uint32_t)(((buf_) * GSTAGE_ + r * GST_ + qd * 4) * 4); \
            cp_async16(sA_u + so, A + (size_t)(m0 + r) * 1024 + k0_ + qd * 4);\
            cp_async16(sB_u + so, W + (size_t)(n0 + r) * 1024 + k0_ + qd * 4);\
        }                                                                     \
    } while (0)

    float acc[4][4][4];
    #pragma unroll
    for (int i = 0; i < 4; i++)
        #pragma unroll
        for (int j = 0; j < 4; j++)
            #pragma unroll
            for (int x = 0; x < 4; x++) acc[i][j][x] = 0.f;

    ISSUE_STAGE(0, 0);
    CP_COMMIT();

    #pragma unroll 1
    for (int s = 0; s < 32; s++) {
        if (s + 1 < 32) {
            ISSUE_STAGE(s + 1, (s + 1) & 1);
            CP_COMMIT();
            CP_WAIT(1);
        } else {
            CP_WAIT(0);
        }
        __syncthreads();

        const float* Ab = Asf + (s & 1) * GSTAGE_;
        const float* Bb = Bsf + (s & 1) * GSTAGE_;
        #pragma unroll
        for (int ks = 0; ks < 4; ks++) {
            const int kc = ks * 8 + tg;
            uint32_t af[4][4];
            #pragma unroll
            for (int mt = 0; mt < 4; mt++) {
                const float* p = Ab + (warpM * 64 + mt * 16 + g) * GST_ + kc;
                af[mt][0] = f2tf32(p[0]);
                af[mt][1] = f2tf32(p[8 * GST_]);
                af[mt][2] = f2tf32(p[4]);
                af[mt][3] = f2tf32(p[8 * GST_ + 4]);
            }
            uint32_t bf[4][2];
            #pragma unroll
            for (int nt = 0; nt < 4; nt++) {
                const float* p = Bb + (warpN * 8 + nt * 32 + g) * GST_ + kc;
                bf[nt][0] = f2tf32(p[0]);
                bf[nt][1] = f2tf32(p[4]);
            }
            #pragma unroll
            for (int mt = 0; mt < 4; mt++)
                #pragma unroll
                for (int nt = 0; nt < 4; nt++)
                    mma_tf32(acc[mt][nt], af[mt], bf[nt]);
        }
        __syncthreads();
    }
    #undef ISSUE_STAGE

    float bcol[4][2];
    #pragma unroll
    for (int nt = 0; nt < 4; nt++) {
        bcol[nt][0] = bias[n0 + warpN * 8 + nt * 32 + 2 * tg + 0];
        bcol[nt][1] = bias[n0 + warpN * 8 + nt * 32 + 2 * tg + 1];
    }
    #pragma unroll
    for (int mt = 0; mt < 4; mt++)
        #pragma unroll
        for (int nt = 0; nt < 4; nt++) {
            acc[mt][nt][0] += bcol[nt][0];
            acc[mt][nt][1] += bcol[nt][1];
            acc[mt][nt][2] += bcol[nt][0];
            acc[mt][nt][3] += bcol[nt][1];
        }

    if (DO_ROPE) {
        float sn[2][8], cs[2][8];
        #pragma unroll
        for (int jj = 0; jj < 2; jj++) {
            int jcol = warpN * 8 + 2 * tg + jj;
            float invf = (float)exp(-(double)jcol * 0.28782313662425574);
            #pragma unroll
            for (int mt = 0; mt < 4; mt++)
                #pragma unroll
                for (int half = 0; half < 2; half++) {
                    int row = m0 + warpM * 64 + mt * 16 + g + 8 * half;
                    float sp = (float)(row & (S_ - 1));
                    sincosf(sp * invf, &sn[jj][mt * 2 + half], &cs[jj][mt * 2 + half]);
                }
        }
        #pragma unroll
        for (int mt = 0; mt < 4; mt++)
            #pragma unroll
            for (int p = 0; p < 2; p++)
                #pragma unroll
                for (int idx = 0; idx < 4; idx++) {
                    int jj = idx & 1, half = idx >> 1;
                    float c = cs[jj][mt * 2 + half], s = sn[jj][mt * 2 + half];
                    float x1 = acc[mt][2 * p][idx], x2 = acc[mt][2 * p + 1][idx];
                    acc[mt][2 * p][idx]     = x1 * c - x2 * s;
                    acc[mt][2 * p + 1][idx] = x1 * s + x2 * c;
                }
    }

    #pragma unroll
    for (int mt = 0; mt < 4; mt++)
        #pragma unroll
        for (int nt = 0; nt < 4; nt++)
            #pragma unroll
            for (int half = 0; half < 2; half++) {
                int row = m0 + warpM * 64 + mt * 16 + g + 8 * half;
                int col = n0 + warpN * 8 + nt * 32 + 2 * tg;
                float2 ov = { acc[mt][nt][half * 2], acc[mt][nt][half * 2 + 1] };
                *(float2*)(C + (size_t)row * 1024 + col) = ov;
            }
}

__global__ __launch_bounds__(256, 2)
void qkv_gemm_mma(const float* __restrict__ q, const float* __restrict__ k,
                  const float* __restrict__ v,
                  const float* __restrict__ Wq, const float* __restrict__ bq,
                  const float* __restrict__ Wk, const float* __restrict__ bk,
                  const float* __restrict__ Wv, const float* __restrict__ bv)
{
    if (blockIdx.z == 0)      gemm_mma_body<1>(q, Wq, bq, g_Qp);
    else if (blockIdx.z == 1) gemm_mma_body<1>(k, Wk, bk, g_Kp);
    else                      gemm_mma_body<0>(v, Wv, bv, g_Vp);
}

__global__ __launch_bounds__(256, 2)
void out_gemm_mma(const float* __restrict__ Wo, const float* __restrict__ bo,
                  float* __restrict__ out)
{
    gemm_mma_body<0>(g_Att, Wo, bo, out);
}

// ---------------------------------------------------------------------------
// Causal flash attention v6: r7-v4 structure scaled to 128 q-rows per CTA.
// 256 threads (8 warps x 16 q-rows), k-tiles of 64, 2xTF32 scores.
//  - Q a-fragments in registers (kt-invariant)
//  - Kraw[2]: fp32 [k][68], cp.async double-buffered prefetch
//  - Vraw:    fp32 [k][68], cp.async single buffer, awaited after softmax
//  - Ps: tf32 [k][132] (128 q + pad; warp-private columns)
// smem = (3*64*68 + 64*132)*4 = 86016 B -> 2 CTAs/SM (16 warps).
// Per-kt fixed costs (3 barriers, K/V tile loads) amortized over 2x q-rows.
// ---------------------------------------------------------------------------
#define AST_ 68
#define PST_ 132
__global__ __launch_bounds__(256, 2) void attn_kernel()
{
    extern __shared__ float afm_[];
    float*    Kraw = afm_;                          // [2][64][68]
    float*    Vraw = afm_ + 2 * 64 * AST_;          // [64][68]
    uint32_t* Ps   = (uint32_t*)(afm_ + 3 * 64 * AST_);  // [64][132]

    const int tid = threadIdx.x;
    const int lane = tid & 31, w = tid >> 5;        // w = 0..7
    const int g = lane >> 2, tg = lane & 3;
    const int qt = 15 - (int)blockIdx.x;            // heavy first (128-row tiles)
    const int h = blockIdx.y, b = blockIdx.z;
    const int ktmax = 2 * qt + 1;

    const float* Qb = g_Qp + ((size_t)b * S_ + qt * 128) * D_ + h * 64;
    const float* Kb = g_Kp + (size_t)b * S_ * D_ + h * 64;
    const float* Vb = g_Vp + (size_t)b * S_ * D_ + h * 64;

    const uint32_t kraw_u = smem_u32(Kraw);
    const uint32_t vraw_u = smem_u32(Vraw);

    #define ISSUE_K(kt_, buf_) do {                                           \
        _Pragma("unroll")                                                     \
        for (int t = 0; t < 4; t++) {                                         \
            int slot = tid + t * 256;                                         \
            int r = slot >> 4, qd = slot & 15;                                \
            uint32_t so = (uint32_t)((((buf_) * 64 + r) * AST_ + qd * 4) * 4);\
            cp_async16(kraw_u + so, Kb + (size_t)((kt_) * 64 + r) * D_ + qd * 4); \
        }                                                                     \
    } while (0)
    #define ISSUE_V(kt_) do {                                                 \
        _Pragma("unroll")                                                     \
        for (int t = 0; t < 4; t++) {                                         \
            int slot = tid + t * 256;                                         \
            int r = slot >> 4, qd = slot & 15;                                \
            uint32_t so = (uint32_t)((r * AST_ + qd * 4) * 4);                \
            cp_async16(vraw_u + so, Vb + (size_t)((kt_) * 64 + r) * D_ + qd * 4); \
        }                                                                     \
    } while (0)

    ISSUE_K(0, 0); CP_COMMIT();

    // ---- Q a-fragments into registers (scaled 1/8, tf32, kt-invariant) ----
    uint32_t qf[8][4];
    {
        const float* q0 = Qb + (size_t)(w * 16 + g) * D_;
        const float* q1 = Qb + (size_t)(w * 16 + g + 8) * D_;
        #pragma unroll
        for (int ks = 0; ks < 8; ks++) {
            int c = ks * 8 + tg;
            qf[ks][0] = f2tf32(q0[c]     * 0.125f);
            qf[ks][1] = f2tf32(q1[c]     * 0.125f);
            qf[ks][2] = f2tf32(q0[c + 4] * 0.125f);
            qf[ks][3] = f2tf32(q1[c + 4] * 0.125f);
        }
    }

    float m[2], l[2], o[8][4];
    m[0] = m[1] = -INFINITY; l[0] = l[1] = 0.f;
    #pragma unroll
    for (int nt = 0; nt < 8; nt++)
        #pragma unroll
        for (int c = 0; c < 4; c++) o[nt][c] = 0.f;

    #pragma unroll 1
    for (int kt = 0; kt <= ktmax; kt++) {
        // prior loop-bottom sync guarantees Vraw / other-K-buf free
        ISSUE_V(kt); CP_COMMIT();
        if (kt + 1 <= ktmax) {
            ISSUE_K(kt + 1, (kt + 1) & 1); CP_COMMIT();
            CP_WAIT(2);               // K(kt) arrived; V(kt), K(kt+1) pending
        } else {
            CP_WAIT(1);               // K(kt) arrived; V(kt) pending
        }
        __syncthreads();

        const float* Kt = Kraw + (kt & 1) * 64 * AST_;

        // ---- S = Q K^T (2xTF32: qh*kh + qh*kl) ----
        float sacc[8][4];
        #pragma unroll
        for (int nt = 0; nt < 8; nt++)
            #pragma unroll
            for (int c = 0; c < 4; c++) sacc[nt][c] = 0.f;

        #pragma unroll
        for (int ks = 0; ks < 8; ks++) {
            #pragma unroll
            for (int nt = 0; nt < 8; nt++) {
                const int bbase = (nt * 8 + g) * AST_ + ks * 8 + tg;
                float b0 = Kt[bbase], b1 = Kt[bbase + 4];
                uint32_t bh[2], bl[2];
                bh[0] = f2tf32(b0); bl[0] = f2tf32(b0 - __uint_as_float(bh[0]));
                bh[1] = f2tf32(b1); bl[1] = f2tf32(b1 - __uint_as_float(bh[1]));
                mma_tf32(sacc[nt], qf[ks], bh);
                mma_tf32(sacc[nt], qf[ks], bl);
            }
        }

        // ---- masking (last two kt tiles cross the diagonal) ----
        if (kt >= 2 * qt) {
            #pragma unroll
            for (int nt = 0; nt < 8; nt++)
                #pragma unroll
                for (int c = 0; c < 4; c++) {
                    int colG = kt * 64 + nt * 8 + 2 * tg + (c & 1);
                    int rowG = qt * 128 + w * 16 + g + 8 * (c >> 1);
                    if (colG > rowG) sacc[nt][c] = -INFINITY;
                }
        }

        // ---- online softmax (rows g, g+8; stats replicated over tg quad) ----
        float rm[2] = {-INFINITY, -INFINITY};
        #pragma unroll
        for (int nt = 0; nt < 8; nt++) {
            rm[0] = fmaxf(rm[0], fmaxf(sacc[nt][0], sacc[nt][1]));
            rm[1] = fmaxf(rm[1], fmaxf(sacc[nt][2], sacc[nt][3]));
        }
        #pragma unroll
        for (int r = 0; r < 2; r++) {
            rm[r] = fmaxf(rm[r], __shfl_xor_sync(0xffffffffu, rm[r], 1));
            rm[r] = fmaxf(rm[r], __shfl_xor_sync(0xffffffffu, rm[r], 2));
        }
        float alpha[2], rs[2];
        #pragma unroll
        for (int r = 0; r < 2; r++) {
            float mn = fmaxf(m[r], rm[r]);
            alpha[r] = __expf(m[r] - mn);
            m[r] = mn;
            rs[r] = 0.f;
        }
        #pragma unroll
        for (int nt = 0; nt < 8; nt++) {
            #pragma unroll
            for (int c = 0; c < 4; c++) {
                int r = c >> 1;
                float p = __expf(sacc[nt][c] - m[r]);
                sacc[nt][c] = p;
                rs[r] += p;
            }
        }
        #pragma unroll
        for (int r = 0; r < 2; r++) {
            rs[r] += __shfl_xor_sync(0xffffffffu, rs[r], 1);
            rs[r] += __shfl_xor_sync(0xffffffffu, rs[r], 2);
            l[r] = l[r] * alpha[r] + rs[r];
        }
        #pragma unroll
        for (int nt = 0; nt < 8; nt++) {
            o[nt][0] *= alpha[0]; o[nt][1] *= alpha[0];
            o[nt][2] *= alpha[1]; o[nt][3] *= alpha[1];
        }

        // ---- store P^T [k][q] (warp-private columns) ----
        #pragma unroll
        for (int nt = 0; nt < 8; nt++)
            #pragma unroll
            for (int c = 0; c < 4; c++) {
                int kpos = nt * 8 + 2 * tg + (c & 1);
                int qrow = w * 16 + g + 8 * (c >> 1);
                Ps[kpos * PST_ + qrow] = f2tf32(sacc[nt][c]);
            }

        // ---- V resident now (hidden behind S + softmax) ----
        if (kt + 1 <= ktmax) { CP_WAIT(1); } else { CP_WAIT(0); }
        __syncthreads();   // V + Ps visible

        // ---- O += P V ----
        #pragma unroll
        for (int ks = 0; ks < 8; ks++) {
            const int pbase = (ks * 8 + tg) * PST_ + w * 16 + g;
            uint32_t pa[4];
            pa[0] = Ps[pbase];
            pa[1] = Ps[pbase + 8];
            pa[2] = Ps[pbase + 4 * PST_];
            pa[3] = Ps[pbase + 4 * PST_ + 8];
            #pragma unroll
            for (int nt = 0; nt < 8; nt++) {
                const int vbase = (ks * 8 + tg) * AST_ + nt * 8 + g;
                uint32_t vb[2];
                vb[0] = f2tf32(Vraw[vbase]);
                vb[1] = f2tf32(Vraw[vbase + 4 * AST_]);
                mma_tf32(o[nt], pa, vb);
            }
        }
        __syncthreads();   // all warps done with V/K/Ps before next kt
    }
    #undef ISSUE_K
    #undef ISSUE_V

    // ---- finalize & store ----
    float inv[2] = { 1.0f / l[0], 1.0f / l[1] };
    float* Ob = g_Att + ((size_t)b * S_ + qt * 128) * D_ + h * 64;
    #pragma unroll
    for (int nt = 0; nt < 8; nt++)
        #pragma unroll
        for (int r = 0; r < 2; r++) {
            int row = w * 16 + g + 8 * r;
            int col = nt * 8 + 2 * tg;
            float2 ov = { o[nt][2 * r] * inv[r], o[nt][2 * r + 1] * inv[r] };
            *(float2*)(Ob + (size_t)row * D_ + col) = ov;
        }
}

// ---------------------------------------------------------------------------
extern "C" void kernel_launch(void* const* d_in, const int* in_sizes, int n_in,
                              void* d_out, int out_size)
{
    (void)in_sizes; (void)n_in; (void)out_size;
    const float* q  = (const float*)d_in[0];
    const float* k  = (const float*)d_in[1];
    const float* v  = (const float*)d_in[2];
    const float* Wq = (const float*)d_in[4];
    const float* bq = (const float*)d_in[5];
    const float* Wk = (const float*)d_in[6];
    const float* bk = (const float*)d_in[7];
    const float* Wv = (const float*)d_in[8];
    const float* bv = (const float*)d_in[9];
    const float* Wo = (const float*)d_in[10];
    const float* bo = (const float*)d_in[11];
    float* out = (float*)d_out;

    const int gemm_smem = 4 * GSTAGE_ * 4;                 // 73728 B (2 stages)
    cudaFuncSetAttribute(qkv_gemm_mma, cudaFuncAttributeMaxDynamicSharedMemorySize, gemm_smem);
    cudaFuncSetAttribute(out_gemm_mma, cudaFuncAttributeMaxDynamicSharedMemorySize, gemm_smem);
    const int attn_smem = (3 * 64 * AST_ + 64 * PST_) * 4; // 86016 B -> 2 CTA/SM
    cudaFuncSetAttribute(attn_kernel, cudaFuncAttributeMaxDynamicSharedMemorySize, attn_smem);

    dim3 gqkv(1024/128, M_/128, 3);
    qkv_gemm_mma<<<gqkv, 256, gemm_smem>>>(q, k, v, Wq, bq, Wk, bk, Wv, bv);

    attn_kernel<<<dim3(S_/128, H_, B_), 256, attn_smem>>>();

    out_gemm_mma<<<dim3(1024/128, M_/128), 256, gemm_smem>>>(Wo, bo, out);
}

// round 10
// speedup vs baseline: 1.7875x; 1.7875x over previous
#include <cuda_runtime.h>
#include <math.h>
#include <stdint.h>

#define B_ 2
#define S_ 2048
#define D_ 1024
#define H_ 16
#define M_ (B_*S_)

// Scratch (allocation-free rule: __device__ globals)
__device__ float g_Qp[(size_t)B_*S_*D_];
__device__ float g_Kp[(size_t)B_*S_*D_];
__device__ float g_Vp[(size_t)B_*S_*D_];
__device__ float g_Att[(size_t)B_*S_*D_];

__device__ __forceinline__ uint32_t f2tf32(float x) {
    uint32_t r;
    asm("cvt.rna.tf32.f32 %0, %1;" : "=r"(r) : "f"(x));
    return r;
}

__device__ __forceinline__ void mma_tf32(float* d, const uint32_t* a, const uint32_t* b) {
    asm volatile(
        "mma.sync.aligned.m16n8k8.row.col.f32.tf32.tf32.f32 "
        "{%0,%1,%2,%3}, {%4,%5,%6,%7}, {%8,%9}, {%0,%1,%2,%3};"
        : "+f"(d[0]), "+f"(d[1]), "+f"(d[2]), "+f"(d[3])
        : "r"(a[0]), "r"(a[1]), "r"(a[2]), "r"(a[3]), "r"(b[0]), "r"(b[1]));
}

__device__ __forceinline__ uint32_t smem_u32(const void* p) {
    uint32_t a;
    asm("{ .reg .u64 t; cvta.to.shared.u64 t, %1; cvt.u32.u64 %0, t; }"
        : "=r"(a) : "l"(p));
    return a;
}

__device__ __forceinline__ void cp_async16(uint32_t saddr, const void* g) {
    asm volatile("cp.async.cg.shared.global [%0], [%1], 16;"
                 :: "r"(saddr), "l"(g) : "memory");
}
#define CP_COMMIT()  asm volatile("cp.async.commit_group;" ::: "memory")
#define CP_WAIT(n_)  asm volatile("cp.async.wait_group %0;" :: "n"(n_) : "memory")

// ---------------------------------------------------------------------------
// tf32 mma.sync GEMM (round-6 2-stage version; best measured 198.9us on qkv)
// CTA 128x128, BK=32, 256 threads (8 warps 2x4), warp tile 64x32.
// cp.async double-buffered raw-fp32 smem [r][k] stride 36 (conflict-free).
// ---------------------------------------------------------------------------
#define GST_ 36
#define GSTAGE_ (128*GST_)

template<int DO_ROPE>
__device__ __forceinline__ void gemm_mma_body(const float* __restrict__ A,
                                              const float* __restrict__ W,
                                              const float* __restrict__ bias,
                                              float* __restrict__ C)
{
    extern __shared__ float gsm_[];
    float* Asf = gsm_;                    // [2][128][36]
    float* Bsf = gsm_ + 2 * GSTAGE_;      // [2][128][36]

    const int tid  = threadIdx.x;
    const int lane = tid & 31, w = tid >> 5;
    const int warpM = w & 1, warpN = w >> 1;
    const int g = lane >> 2, tg = lane & 3;
    const int m0 = blockIdx.y * 128, n0 = blockIdx.x * 128;

    const uint32_t sA_u = smem_u32(Asf);
    const uint32_t sB_u = smem_u32(Bsf);

    #define ISSUE_STAGE(s_, buf_) do {                                        \
        const int k0_ = (s_) * 32;                                            \
        _Pragma("unroll")                                                     \
        for (int t = 0; t < 4; t++) {                                         \
            int slot = tid + t * 256;                                         \
            int r = slot >> 3, qd = slot & 7;                                 \
            uint32_t so = (uint32_t)(((buf_) * GSTAGE_ + r * GST_ + qd * 4) * 4); \
            cp_async16(sA_u + so, A + (size_t)(m0 + r) * 1024 + k0_ + qd * 4);\
            cp_async16(sB_u + so, W + (size_t)(n0 + r) * 1024 + k0_ + qd * 4);\
        }                                                                     \
    } while (0)

    float acc[4][4][4];
    #pragma unroll
    for (int i = 0; i < 4; i++)
        #pragma unroll
        for (int j = 0; j < 4; j++)
            #pragma unroll
            for (int x = 0; x < 4; x++) acc[i][j][x] = 0.f;

    ISSUE_STAGE(0, 0);
    CP_COMMIT();

    #pragma unroll 1
    for (int s = 0; s < 32; s++) {
        if (s + 1 < 32) {
            ISSUE_STAGE(s + 1, (s + 1) & 1);
            CP_COMMIT();
            CP_WAIT(1);
        } else {
            CP_WAIT(0);
        }
        __syncthreads();

        const float* Ab = Asf + (s & 1) * GSTAGE_;
        const float* Bb = Bsf + (s & 1) * GSTAGE_;
        #pragma unroll
        for (int ks = 0; ks < 4; ks++) {
            const int kc = ks * 8 + tg;
            uint32_t af[4][4];
            #pragma unroll
            for (int mt = 0; mt < 4; mt++) {
                const float* p = Ab + (warpM * 64 + mt * 16 + g) * GST_ + kc;
                af[mt][0] = f2tf32(p[0]);
                af[mt][1] = f2tf32(p[8 * GST_]);
                af[mt][2] = f2tf32(p[4]);
                af[mt][3] = f2tf32(p[8 * GST_ + 4]);
            }
            uint32_t bf[4][2];
            #pragma unroll
            for (int nt = 0; nt < 4; nt++) {
                const float* p = Bb + (warpN * 8 + nt * 32 + g) * GST_ + kc;
                bf[nt][0] = f2tf32(p[0]);
                bf[nt][1] = f2tf32(p[4]);
            }
            #pragma unroll
            for (int mt = 0; mt < 4; mt++)
                #pragma unroll
                for (int nt = 0; nt < 4; nt++)
                    mma_tf32(acc[mt][nt], af[mt], bf[nt]);
        }
        __syncthreads();
    }
    #undef ISSUE_STAGE

    float bcol[4][2];
    #pragma unroll
    for (int nt = 0; nt < 4; nt++) {
        bcol[nt][0] = bias[n0 + warpN * 8 + nt * 32 + 2 * tg + 0];
        bcol[nt][1] = bias[n0 + warpN * 8 + nt * 32 + 2 * tg + 1];
    }
    #pragma unroll
    for (int mt = 0; mt < 4; mt++)
        #pragma unroll
        for (int nt = 0; nt < 4; nt++) {
            acc[mt][nt][0] += bcol[nt][0];
            acc[mt][nt][1] += bcol[nt][1];
            acc[mt][nt][2] += bcol[nt][0];
            acc[mt][nt][3] += bcol[nt][1];
        }

    if (DO_ROPE) {
        float sn[2][8], cs[2][8];
        #pragma unroll
        for (int jj = 0; jj < 2; jj++) {
            int jcol = warpN * 8 + 2 * tg + jj;
            float invf = (float)exp(-(double)jcol * 0.28782313662425574);
            #pragma unroll
            for (int mt = 0; mt < 4; mt++)
                #pragma unroll
                for (int half = 0; half < 2; half++) {
                    int row = m0 + warpM * 64 + mt * 16 + g + 8 * half;
                    float sp = (float)(row & (S_ - 1));
                    sincosf(sp * invf, &sn[jj][mt * 2 + half], &cs[jj][mt * 2 + half]);
                }
        }
        #pragma unroll
        for (int mt = 0; mt < 4; mt++)
            #pragma unroll
            for (int p = 0; p < 2; p++)
                #pragma unroll
                for (int idx = 0; idx < 4; idx++) {
                    int jj = idx & 1, half = idx >> 1;
                    float c = cs[jj][mt * 2 + half], s = sn[jj][mt * 2 + half];
                    float x1 = acc[mt][2 * p][idx], x2 = acc[mt][2 * p + 1][idx];
                    acc[mt][2 * p][idx]     = x1 * c - x2 * s;
                    acc[mt][2 * p + 1][idx] = x1 * s + x2 * c;
                }
    }

    #pragma unroll
    for (int mt = 0; mt < 4; mt++)
        #pragma unroll
        for (int nt = 0; nt < 4; nt++)
            #pragma unroll
            for (int half = 0; half < 2; half++) {
                int row = m0 + warpM * 64 + mt * 16 + g + 8 * half;
                int col = n0 + warpN * 8 + nt * 32 + 2 * tg;
                float2 ov = { acc[mt][nt][half * 2], acc[mt][nt][half * 2 + 1] };
                *(float2*)(C + (size_t)row * 1024 + col) = ov;
            }
}

__global__ __launch_bounds__(256, 2)
void qkv_gemm_mma(const float* __restrict__ q, const float* __restrict__ k,
                  const float* __restrict__ v,
                  const float* __restrict__ Wq, const float* __restrict__ bq,
                  const float* __restrict__ Wk, const float* __restrict__ bk,
                  const float* __restrict__ Wv, const float* __restrict__ bv)
{
    if (blockIdx.z == 0)      gemm_mma_body<1>(q, Wq, bq, g_Qp);
    else if (blockIdx.z == 1) gemm_mma_body<1>(k, Wk, bk, g_Kp);
    else                      gemm_mma_body<0>(v, Wv, bv, g_Vp);
}

__global__ __launch_bounds__(256, 2)
void out_gemm_mma(const float* __restrict__ Wo, const float* __restrict__ bo,
                  float* __restrict__ out)
{
    gemm_mma_body<0>(g_Att, Wo, bo, out);
}

// ---------------------------------------------------------------------------
// Causal flash attention v4 (round-7 exact; best measured ~277us):
// 128 threads, 64x64 tiles, 2xTF32 scores.
//  - Q a-fragments in registers (kt-invariant)
//  - Kraw[2]: fp32 [k][d], cp.async double-buffered prefetch
//  - Vraw:    fp32 [k][d], cp.async single buffer, issued at kt-top,
//             awaited only after softmax (hidden behind S-phase)
//  - Ps: tf32 [k][q]
// smem = 4*64*68*4 = 69632 B -> 3 CTAs/SM (12 warps) WITH prefetch.
// ---------------------------------------------------------------------------
#define AST_ 68
__global__ __launch_bounds__(128, 3) void attn_kernel()
{
    extern __shared__ float afm_[];
    float*    Kraw = afm_;                          // [2][64][68]
    float*    Vraw = afm_ + 2 * 64 * AST_;          // [64][68]
    uint32_t* Ps   = (uint32_t*)(afm_ + 3 * 64 * AST_);

    const int tid = threadIdx.x;
    const int lane = tid & 31, w = tid >> 5;
    const int g = lane >> 2, tg = lane & 3;
    const int qt = (int)(gridDim.x - 1) - (int)blockIdx.x;   // heavy first
    const int h = blockIdx.y, b = blockIdx.z;

    const float* Qb = g_Qp + ((size_t)b * S_ + qt * 64) * D_ + h * 64;
    const float* Kb = g_Kp + (size_t)b * S_ * D_ + h * 64;
    const float* Vb = g_Vp + (size_t)b * S_ * D_ + h * 64;

    const uint32_t kraw_u = smem_u32(Kraw);
    const uint32_t vraw_u = smem_u32(Vraw);

    #define ISSUE_K(kt_, buf_) do {                                           \
        _Pragma("unroll")                                                     \
        for (int t = 0; t < 8; t++) {                                         \
            int slot = tid + t * 128;                                         \
            int r = slot >> 4, qd = slot & 15;                                \
            uint32_t so = (uint32_t)((((buf_) * 64 + r) * AST_ + qd * 4) * 4);\
            cp_async16(kraw_u + so, Kb + (size_t)((kt_) * 64 + r) * D_ + qd * 4); \
        }                                                                     \
    } while (0)
    #define ISSUE_V(kt_) do {                                                 \
        _Pragma("unroll")                                                     \
        for (int t = 0; t < 8; t++) {                                         \
            int slot = tid + t * 128;                                         \
            int r = slot >> 4, qd = slot & 15;                                \
            uint32_t so = (uint32_t)((r * AST_ + qd * 4) * 4);                \
            cp_async16(vraw_u + so, Vb + (size_t)((kt_) * 64 + r) * D_ + qd * 4); \
        }                                                                     \
    } while (0)

    ISSUE_K(0, 0); CP_COMMIT();

    // ---- Q a-fragments into registers (scaled 1/8, tf32, kt-invariant) ----
    uint32_t qf[8][4];
    {
        const float* q0 = Qb + (size_t)(w * 16 + g) * D_;
        const float* q1 = Qb + (size_t)(w * 16 + g + 8) * D_;
        #pragma unroll
        for (int ks = 0; ks < 8; ks++) {
            int c = ks * 8 + tg;
            qf[ks][0] = f2tf32(q0[c]     * 0.125f);
            qf[ks][1] = f2tf32(q1[c]     * 0.125f);
            qf[ks][2] = f2tf32(q0[c + 4] * 0.125f);
            qf[ks][3] = f2tf32(q1[c + 4] * 0.125f);
        }
    }

    float m[2], l[2], o[8][4];
    m[0] = m[1] = -INFINITY; l[0] = l[1] = 0.f;
    #pragma unroll
    for (int nt = 0; nt < 8; nt++)
        #pragma unroll
        for (int c = 0; c < 4; c++) o[nt][c] = 0.f;

    #pragma unroll 1
    for (int kt = 0; kt <= qt; kt++) {
        // prior end-of-loop sync guarantees Vraw/Ps/other-K-buf free
        ISSUE_V(kt); CP_COMMIT();
        if (kt + 1 <= qt) {
            ISSUE_K(kt + 1, (kt + 1) & 1); CP_COMMIT();
            CP_WAIT(2);               // K(kt) arrived; V(kt), K(kt+1) pending
        } else {
            CP_WAIT(1);               // K(kt) arrived; V(kt) pending
        }
        __syncthreads();

        const float* Kt = Kraw + (kt & 1) * 64 * AST_;

        // ---- S = Q K^T (2xTF32: qh*kh + qh*kl) ----
        float sacc[8][4];
        #pragma unroll
        for (int nt = 0; nt < 8; nt++)
            #pragma unroll
            for (int c = 0; c < 4; c++) sacc[nt][c] = 0.f;

        #pragma unroll
        for (int ks = 0; ks < 8; ks++) {
            #pragma unroll
            for (int nt = 0; nt < 8; nt++) {
                const int bbase = (nt * 8 + g) * AST_ + ks * 8 + tg;
                float b0 = Kt[bbase], b1 = Kt[bbase + 4];
                uint32_t bh[2], bl[2];
                bh[0] = f2tf32(b0); bl[0] = f2tf32(b0 - __uint_as_float(bh[0]));
                bh[1] = f2tf32(b1); bl[1] = f2tf32(b1 - __uint_as_float(bh[1]));
                mma_tf32(sacc[nt], qf[ks], bh);
                mma_tf32(sacc[nt], qf[ks], bl);
            }
        }

        // ---- masking (diag tile only) ----
        if (kt == qt) {
            #pragma unroll
            for (int nt = 0; nt < 8; nt++)
                #pragma unroll
                for (int c = 0; c < 4; c++) {
                    int colL = nt * 8 + 2 * tg + (c & 1);
                    int rowL = w * 16 + g + 8 * (c >> 1);
                    if (colL > rowL) sacc[nt][c] = -INFINITY;
                }
        }

        // ---- online softmax (rows g, g+8; stats replicated over tg quad) ----
        float rm[2] = {-INFINITY, -INFINITY};
        #pragma unroll
        for (int nt = 0; nt < 8; nt++) {
            rm[0] = fmaxf(rm[0], fmaxf(sacc[nt][0], sacc[nt][1]));
            rm[1] = fmaxf(rm[1], fmaxf(sacc[nt][2], sacc[nt][3]));
        }
        #pragma unroll
        for (int r = 0; r < 2; r++) {
            rm[r] = fmaxf(rm[r], __shfl_xor_sync(0xffffffffu, rm[r], 1));
            rm[r] = fmaxf(rm[r], __shfl_xor_sync(0xffffffffu, rm[r], 2));
        }
        float alpha[2], rs[2];
        #pragma unroll
        for (int r = 0; r < 2; r++) {
            float mn = fmaxf(m[r], rm[r]);
            alpha[r] = __expf(m[r] - mn);
            m[r] = mn;
            rs[r] = 0.f;
        }
        #pragma unroll
        for (int nt = 0; nt < 8; nt++) {
            #pragma unroll
            for (int c = 0; c < 4; c++) {
                int r = c >> 1;
                float p = __expf(sacc[nt][c] - m[r]);
                sacc[nt][c] = p;
                rs[r] += p;
            }
        }
        #pragma unroll
        for (int r = 0; r < 2; r++) {
            rs[r] += __shfl_xor_sync(0xffffffffu, rs[r], 1);
            rs[r] += __shfl_xor_sync(0xffffffffu, rs[r], 2);
            l[r] = l[r] * alpha[r] + rs[r];
        }
        #pragma unroll
        for (int nt = 0; nt < 8; nt++) {
            o[nt][0] *= alpha[0]; o[nt][1] *= alpha[0];
            o[nt][2] *= alpha[1]; o[nt][3] *= alpha[1];
        }

        // ---- store P^T [k][q] (warp-private columns) ----
        #pragma unroll
        for (int nt = 0; nt < 8; nt++)
            #pragma unroll
            for (int c = 0; c < 4; c++) {
                int kpos = nt * 8 + 2 * tg + (c & 1);
                int qrow = w * 16 + g + 8 * (c >> 1);
                Ps[kpos * AST_ + qrow] = f2tf32(sacc[nt][c]);
            }

        // ---- V must be resident now (was hidden behind S + softmax) ----
        if (kt + 1 <= qt) { CP_WAIT(1); } else { CP_WAIT(0); }
        __syncthreads();   // V + Ps visible to all warps

        // ---- O += P V ----
        #pragma unroll
        for (int ks = 0; ks < 8; ks++) {
            const int pbase = (ks * 8 + tg) * AST_ + w * 16 + g;
            uint32_t pa[4];
            pa[0] = Ps[pbase];
            pa[1] = Ps[pbase + 8];
            pa[2] = Ps[pbase + 4 * AST_];
            pa[3] = Ps[pbase + 4 * AST_ + 8];
            #pragma unroll
            for (int nt = 0; nt < 8; nt++) {
                const int vbase = (ks * 8 + tg) * AST_ + nt * 8 + g;
                uint32_t vb[2];
                vb[0] = f2tf32(Vraw[vbase]);
                vb[1] = f2tf32(Vraw[vbase + 4 * AST_]);
                mma_tf32(o[nt], pa, vb);
            }
        }
        __syncthreads();   // all warps done with V/K/Ps before next kt's issues
    }
    #undef ISSUE_K
    #undef ISSUE_V

    // ---- finalize & store ----
    float inv[2] = { 1.0f / l[0], 1.0f / l[1] };
    float* Ob = g_Att + ((size_t)b * S_ + qt * 64) * D_ + h * 64;
    #pragma unroll
    for (int nt = 0; nt < 8; nt++)
        #pragma unroll
        for (int r = 0; r < 2; r++) {
            int row = w * 16 + g + 8 * r;
            int col = nt * 8 + 2 * tg;
            float2 ov = { o[nt][2 * r] * inv[r], o[nt][2 * r + 1] * inv[r] };
            *(float2*)(Ob + (size_t)row * D_ + col) = ov;
        }
}

// ---------------------------------------------------------------------------
extern "C" void kernel_launch(void* const* d_in, const int* in_sizes, int n_in,
                              void* d_out, int out_size)
{
    (void)in_sizes; (void)n_in; (void)out_size;
    const float* q  = (const float*)d_in[0];
    const float* k  = (const float*)d_in[1];
    const float* v  = (const float*)d_in[2];
    const float* Wq = (const float*)d_in[4];
    const float* bq = (const float*)d_in[5];
    const float* Wk = (const float*)d_in[6];
    const float* bk = (const float*)d_in[7];
    const float* Wv = (const float*)d_in[8];
    const float* bv = (const float*)d_in[9];
    const float* Wo = (const float*)d_in[10];
    const float* bo = (const float*)d_in[11];
    float* out = (float*)d_out;

    const int gemm_smem = 4 * GSTAGE_ * 4;           // 73728 B (2 stages)
    cudaFuncSetAttribute(qkv_gemm_mma, cudaFuncAttributeMaxDynamicSharedMemorySize, gemm_smem);
    cudaFuncSetAttribute(out_gemm_mma, cudaFuncAttributeMaxDynamicSharedMemorySize, gemm_smem);
    const int attn_smem = 4 * 64 * AST_ * 4;         // 69632 B -> 3 CTA/SM
    cudaFuncSetAttribute(attn_kernel, cudaFuncAttributeMaxDynamicSharedMemorySize, attn_smem);

    dim3 gqkv(1024/128, M_/128, 3);
    qkv_gemm_mma<<<gqkv, 256, gemm_smem>>>(q, k, v, Wq, bq, Wk, bk, Wv, bv);

    attn_kernel<<<dim3(S_/64, H_, B_), 128, attn_smem>>>();

    out_gemm_mma<<<dim3(1024/128, M_/128), 256, gemm_smem>>>(Wo, bo, out);
}

// round 11
// speedup vs baseline: 2.0349x; 1.1385x over previous
#include <cuda_runtime.h>
#include <math.h>
#include <stdint.h>

#define B_ 2
#define S_ 2048
#define D_ 1024
#define H_ 16
#define M_ (B_*S_)

// Scratch (allocation-free rule: __device__ globals)
__device__ float g_Qp[(size_t)B_*S_*D_];
__device__ float g_Kp[(size_t)B_*S_*D_];
__device__ float g_Vp[(size_t)B_*S_*D_];
__device__ float g_Att[(size_t)B_*S_*D_];

__device__ __forceinline__ uint32_t f2tf32(float x) {
    uint32_t r;
    asm("cvt.rna.tf32.f32 %0, %1;" : "=r"(r) : "f"(x));
    return r;
}

__device__ __forceinline__ void mma_tf32(float* d, const uint32_t* a, const uint32_t* b) {
    asm volatile(
        "mma.sync.aligned.m16n8k8.row.col.f32.tf32.tf32.f32 "
        "{%0,%1,%2,%3}, {%4,%5,%6,%7}, {%8,%9}, {%0,%1,%2,%3};"
        : "+f"(d[0]), "+f"(d[1]), "+f"(d[2]), "+f"(d[3])
        : "r"(a[0]), "r"(a[1]), "r"(a[2]), "r"(a[3]), "r"(b[0]), "r"(b[1]));
}

__device__ __forceinline__ uint32_t smem_u32(const void* p) {
    uint32_t a;
    asm("{ .reg .u64 t; cvta.to.shared.u64 t, %1; cvt.u32.u64 %0, t; }"
        : "=r"(a) : "l"(p));
    return a;
}

__device__ __forceinline__ void cp_async16(uint32_t saddr, const void* g) {
    asm volatile("cp.async.cg.shared.global [%0], [%1], 16;"
                 :: "r"(saddr), "l"(g) : "memory");
}
#define CP_COMMIT()  asm volatile("cp.async.commit_group;" ::: "memory")
#define CP_WAIT(n_)  asm volatile("cp.async.wait_group %0;" :: "n"(n_) : "memory")

// ---------------------------------------------------------------------------
// tf32 mma.sync GEMM (round-6 2-stage version; best measured 198.0us on qkv)
// CTA 128x128, BK=32, 256 threads (8 warps 2x4), warp tile 64x32.
// cp.async double-buffered raw-fp32 smem [r][k] stride 36 (conflict-free).
// ---------------------------------------------------------------------------
#define GST_ 36
#define GSTAGE_ (128*GST_)

template<int DO_ROPE>
__device__ __forceinline__ void gemm_mma_body(const float* __restrict__ A,
                                              const float* __restrict__ W,
                                              const float* __restrict__ bias,
                                              float* __restrict__ C)
{
    extern __shared__ float gsm_[];
    float* Asf = gsm_;                    // [2][128][36]
    float* Bsf = gsm_ + 2 * GSTAGE_;      // [2][128][36]

    const int tid  = threadIdx.x;
    const int lane = tid & 31, w = tid >> 5;
    const int warpM = w & 1, warpN = w >> 1;
    const int g = lane >> 2, tg = lane & 3;
    const int m0 = blockIdx.y * 128, n0 = blockIdx.x * 128;

    const uint32_t sA_u = smem_u32(Asf);
    const uint32_t sB_u = smem_u32(Bsf);

    #define ISSUE_STAGE(s_, buf_) do {                                        \
        const int k0_ = (s_) * 32;                                            \
        _Pragma("unroll")                                                     \
        for (int t = 0; t < 4; t++) {                                         \
            int slot = tid + t * 256;                                         \
            int r = slot >> 3, qd = slot & 7;                                 \
            uint32_t so = (uint32_t)(((buf_) * GSTAGE_ + r * GST_ + qd * 4) * 4); \
            cp_async16(sA_u + so, A + (size_t)(m0 + r) * 1024 + k0_ + qd * 4);\
            cp_async16(sB_u + so, W + (size_t)(n0 + r) * 1024 + k0_ + qd * 4);\
        }                                                                     \
    } while (0)

    float acc[4][4][4];
    #pragma unroll
    for (int i = 0; i < 4; i++)
        #pragma unroll
        for (int j = 0; j < 4; j++)
            #pragma unroll
            for (int x = 0; x < 4; x++) acc[i][j][x] = 0.f;

    ISSUE_STAGE(0, 0);
    CP_COMMIT();

    #pragma unroll 1
    for (int s = 0; s < 32; s++) {
        if (s + 1 < 32) {
            ISSUE_STAGE(s + 1, (s + 1) & 1);
            CP_COMMIT();
            CP_WAIT(1);
        } else {
            CP_WAIT(0);
        }
        __syncthreads();

        const float* Ab = Asf + (s & 1) * GSTAGE_;
        const float* Bb = Bsf + (s & 1) * GSTAGE_;
        #pragma unroll
        for (int ks = 0; ks < 4; ks++) {
            const int kc = ks * 8 + tg;
            uint32_t af[4][4];
            #pragma unroll
            for (int mt = 0; mt < 4; mt++) {
                const float* p = Ab + (warpM * 64 + mt * 16 + g) * GST_ + kc;
                af[mt][0] = f2tf32(p[0]);
                af[mt][1] = f2tf32(p[8 * GST_]);
                af[mt][2] = f2tf32(p[4]);
                af[mt][3] = f2tf32(p[8 * GST_ + 4]);
            }
            uint32_t bf[4][2];
            #pragma unroll
            for (int nt = 0; nt < 4; nt++) {
                const float* p = Bb + (warpN * 8 + nt * 32 + g) * GST_ + kc;
                bf[nt][0] = f2tf32(p[0]);
                bf[nt][1] = f2tf32(p[4]);
            }
            #pragma unroll
            for (int mt = 0; mt < 4; mt++)
                #pragma unroll
                for (int nt = 0; nt < 4; nt++)
                    mma_tf32(acc[mt][nt], af[mt], bf[nt]);
        }
        __syncthreads();
    }
    #undef ISSUE_STAGE

    float bcol[4][2];
    #pragma unroll
    for (int nt = 0; nt < 4; nt++) {
        bcol[nt][0] = bias[n0 + warpN * 8 + nt * 32 + 2 * tg + 0];
        bcol[nt][1] = bias[n0 + warpN * 8 + nt * 32 + 2 * tg + 1];
    }
    #pragma unroll
    for (int mt = 0; mt < 4; mt++)
        #pragma unroll
        for (int nt = 0; nt < 4; nt++) {
            acc[mt][nt][0] += bcol[nt][0];
            acc[mt][nt][1] += bcol[nt][1];
            acc[mt][nt][2] += bcol[nt][0];
            acc[mt][nt][3] += bcol[nt][1];
        }

    if (DO_ROPE) {
        float sn[2][8], cs[2][8];
        #pragma unroll
        for (int jj = 0; jj < 2; jj++) {
            int jcol = warpN * 8 + 2 * tg + jj;
            float invf = (float)exp(-(double)jcol * 0.28782313662425574);
            #pragma unroll
            for (int mt = 0; mt < 4; mt++)
                #pragma unroll
                for (int half = 0; half < 2; half++) {
                    int row = m0 + warpM * 64 + mt * 16 + g + 8 * half;
                    float sp = (float)(row & (S_ - 1));
                    sincosf(sp * invf, &sn[jj][mt * 2 + half], &cs[jj][mt * 2 + half]);
                }
        }
        #pragma unroll
        for (int mt = 0; mt < 4; mt++)
            #pragma unroll
            for (int p = 0; p < 2; p++)
                #pragma unroll
                for (int idx = 0; idx < 4; idx++) {
                    int jj = idx & 1, half = idx >> 1;
                    float c = cs[jj][mt * 2 + half], s = sn[jj][mt * 2 + half];
                    float x1 = acc[mt][2 * p][idx], x2 = acc[mt][2 * p + 1][idx];
                    acc[mt][2 * p][idx]     = x1 * c - x2 * s;
                    acc[mt][2 * p + 1][idx] = x1 * s + x2 * c;
                }
    }

    #pragma unroll
    for (int mt = 0; mt < 4; mt++)
        #pragma unroll
        for (int nt = 0; nt < 4; nt++)
            #pragma unroll
            for (int half = 0; half < 2; half++) {
                int row = m0 + warpM * 64 + mt * 16 + g + 8 * half;
                int col = n0 + warpN * 8 + nt * 32 + 2 * tg;
                float2 ov = { acc[mt][nt][half * 2], acc[mt][nt][half * 2 + 1] };
                *(float2*)(C + (size_t)row * 1024 + col) = ov;
            }
}

__global__ __launch_bounds__(256, 2)
void qkv_gemm_mma(const float* __restrict__ q, const float* __restrict__ k,
                  const float* __restrict__ v,
                  const float* __restrict__ Wq, const float* __restrict__ bq,
                  const float* __restrict__ Wk, const float* __restrict__ bk,
                  const float* __restrict__ Wv, const float* __restrict__ bv)
{
    if (blockIdx.z == 0)      gemm_mma_body<1>(q, Wq, bq, g_Qp);
    else if (blockIdx.z == 1) gemm_mma_body<1>(k, Wk, bk, g_Kp);
    else                      gemm_mma_body<0>(v, Wv, bv, g_Vp);
}

__global__ __launch_bounds__(256, 2)
void out_gemm_mma(const float* __restrict__ Wo, const float* __restrict__ bo,
                  float* __restrict__ out)
{
    gemm_mma_body<0>(g_Att, Wo, bo, out);
}

// ---------------------------------------------------------------------------
// Causal flash attention v7: round-7 v4 structure, S-phase now 1xTF32
// (K plain tf32; K-lo term dropped — error ledger predicts ~6.7e-4 total).
// 128 threads, 64x64 tiles.
//  - Q a-fragments in registers (kt-invariant, scaled 1/8)
//  - Kraw[2]: fp32 [k][d], cp.async double-buffered prefetch
//  - Vraw:    fp32 [k][d], cp.async single buffer, awaited after softmax
//  - Ps: tf32 [k][q]
// smem = 4*64*68*4 = 69632 B -> 3 CTAs/SM.
// ---------------------------------------------------------------------------
#define AST_ 68
__global__ __launch_bounds__(128, 3) void attn_kernel()
{
    extern __shared__ float afm_[];
    float*    Kraw = afm_;                          // [2][64][68]
    float*    Vraw = afm_ + 2 * 64 * AST_;          // [64][68]
    uint32_t* Ps   = (uint32_t*)(afm_ + 3 * 64 * AST_);

    const int tid = threadIdx.x;
    const int lane = tid & 31, w = tid >> 5;
    const int g = lane >> 2, tg = lane & 3;
    const int qt = (int)(gridDim.x - 1) - (int)blockIdx.x;   // heavy first
    const int h = blockIdx.y, b = blockIdx.z;

    const float* Qb = g_Qp + ((size_t)b * S_ + qt * 64) * D_ + h * 64;
    const float* Kb = g_Kp + (size_t)b * S_ * D_ + h * 64;
    const float* Vb = g_Vp + (size_t)b * S_ * D_ + h * 64;

    const uint32_t kraw_u = smem_u32(Kraw);
    const uint32_t vraw_u = smem_u32(Vraw);

    #define ISSUE_K(kt_, buf_) do {                                           \
        _Pragma("unroll")                                                     \
        for (int t = 0; t < 8; t++) {                                         \
            int slot = tid + t * 128;                                         \
            int r = slot >> 4, qd = slot & 15;                                \
            uint32_t so = (uint32_t)((((buf_) * 64 + r) * AST_ + qd * 4) * 4);\
            cp_async16(kraw_u + so, Kb + (size_t)((kt_) * 64 + r) * D_ + qd * 4); \
        }                                                                     \
    } while (0)
    #define ISSUE_V(kt_) do {                                                 \
        _Pragma("unroll")                                                     \
        for (int t = 0; t < 8; t++) {                                         \
            int slot = tid + t * 128;                                         \
            int r = slot >> 4, qd = slot & 15;                                \
            uint32_t so = (uint32_t)((r * AST_ + qd * 4) * 4);                \
            cp_async16(vraw_u + so, Vb + (size_t)((kt_) * 64 + r) * D_ + qd * 4); \
        }                                                                     \
    } while (0)

    ISSUE_K(0, 0); CP_COMMIT();

    // ---- Q a-fragments into registers (scaled 1/8, tf32, kt-invariant) ----
    uint32_t qf[8][4];
    {
        const float* q0 = Qb + (size_t)(w * 16 + g) * D_;
        const float* q1 = Qb + (size_t)(w * 16 + g + 8) * D_;
        #pragma unroll
        for (int ks = 0; ks < 8; ks++) {
            int c = ks * 8 + tg;
            qf[ks][0] = f2tf32(q0[c]     * 0.125f);
            qf[ks][1] = f2tf32(q1[c]     * 0.125f);
            qf[ks][2] = f2tf32(q0[c + 4] * 0.125f);
            qf[ks][3] = f2tf32(q1[c + 4] * 0.125f);
        }
    }

    float m[2], l[2], o[8][4];
    m[0] = m[1] = -INFINITY; l[0] = l[1] = 0.f;
    #pragma unroll
    for (int nt = 0; nt < 8; nt++)
        #pragma unroll
        for (int c = 0; c < 4; c++) o[nt][c] = 0.f;

    #pragma unroll 1
    for (int kt = 0; kt <= qt; kt++) {
        // prior end-of-loop sync guarantees Vraw/Ps/other-K-buf free
        ISSUE_V(kt); CP_COMMIT();
        if (kt + 1 <= qt) {
            ISSUE_K(kt + 1, (kt + 1) & 1); CP_COMMIT();
            CP_WAIT(2);               // K(kt) arrived; V(kt), K(kt+1) pending
        } else {
            CP_WAIT(1);               // K(kt) arrived; V(kt) pending
        }
        __syncthreads();

        const float* Kt = Kraw + (kt & 1) * 64 * AST_;

        // ---- S = Q K^T (1xTF32: both operands plain tf32) ----
        float sacc[8][4];
        #pragma unroll
        for (int nt = 0; nt < 8; nt++)
            #pragma unroll
            for (int c = 0; c < 4; c++) sacc[nt][c] = 0.f;

        #pragma unroll
        for (int ks = 0; ks < 8; ks++) {
            #pragma unroll
            for (int nt = 0; nt < 8; nt++) {
                const int bbase = (nt * 8 + g) * AST_ + ks * 8 + tg;
                uint32_t bh[2];
                bh[0] = f2tf32(Kt[bbase]);
                bh[1] = f2tf32(Kt[bbase + 4]);
                mma_tf32(sacc[nt], qf[ks], bh);
            }
        }

        // ---- masking (diag tile only) ----
        if (kt == qt) {
            #pragma unroll
            for (int nt = 0; nt < 8; nt++)
                #pragma unroll
                for (int c = 0; c < 4; c++) {
                    int colL = nt * 8 + 2 * tg + (c & 1);
                    int rowL = w * 16 + g + 8 * (c >> 1);
                    if (colL > rowL) sacc[nt][c] = -INFINITY;
                }
        }

        // ---- online softmax (rows g, g+8; stats replicated over tg quad) ----
        float rm[2] = {-INFINITY, -INFINITY};
        #pragma unroll
        for (int nt = 0; nt < 8; nt++) {
            rm[0] = fmaxf(rm[0], fmaxf(sacc[nt][0], sacc[nt][1]));
            rm[1] = fmaxf(rm[1], fmaxf(sacc[nt][2], sacc[nt][3]));
        }
        #pragma unroll
        for (int r = 0; r < 2; r++) {
            rm[r] = fmaxf(rm[r], __shfl_xor_sync(0xffffffffu, rm[r], 1));
            rm[r] = fmaxf(rm[r], __shfl_xor_sync(0xffffffffu, rm[r], 2));
        }
        float alpha[2], rs[2];
        #pragma unroll
        for (int r = 0; r < 2; r++) {
            float mn = fmaxf(m[r], rm[r]);
            alpha[r] = __expf(m[r] - mn);
            m[r] = mn;
            rs[r] = 0.f;
        }
        #pragma unroll
        for (int nt = 0; nt < 8; nt++) {
            #pragma unroll
            for (int c = 0; c < 4; c++) {
                int r = c >> 1;
                float p = __expf(sacc[nt][c] - m[r]);
                sacc[nt][c] = p;
                rs[r] += p;
            }
        }
        #pragma unroll
        for (int r = 0; r < 2; r++) {
            rs[r] += __shfl_xor_sync(0xffffffffu, rs[r], 1);
            rs[r] += __shfl_xor_sync(0xffffffffu, rs[r], 2);
            l[r] = l[r] * alpha[r] + rs[r];
        }
        #pragma unroll
        for (int nt = 0; nt < 8; nt++) {
            o[nt][0] *= alpha[0]; o[nt][1] *= alpha[0];
            o[nt][2] *= alpha[1]; o[nt][3] *= alpha[1];
        }

        // ---- store P^T [k][q] (warp-private columns) ----
        #pragma unroll
        for (int nt = 0; nt < 8; nt++)
            #pragma unroll
            for (int c = 0; c < 4; c++) {
                int kpos = nt * 8 + 2 * tg + (c & 1);
                int qrow = w * 16 + g + 8 * (c >> 1);
                Ps[kpos * AST_ + qrow] = f2tf32(sacc[nt][c]);
            }

        // ---- V must be resident now (was hidden behind S + softmax) ----
        if (kt + 1 <= qt) { CP_WAIT(1); } else { CP_WAIT(0); }
        __syncthreads();   // V + Ps visible to all warps

        // ---- O += P V ----
        #pragma unroll
        for (int ks = 0; ks < 8; ks++) {
            const int pbase = (ks * 8 + tg) * AST_ + w * 16 + g;
            uint32_t pa[4];
            pa[0] = Ps[pbase];
            pa[1] = Ps[pbase + 8];
            pa[2] = Ps[pbase + 4 * AST_];
            pa[3] = Ps[pbase + 4 * AST_ + 8];
            #pragma unroll
            for (int nt = 0; nt < 8; nt++) {
                const int vbase = (ks * 8 + tg) * AST_ + nt * 8 + g;
                uint32_t vb[2];
                vb[0] = f2tf32(Vraw[vbase]);
                vb[1] = f2tf32(Vraw[vbase + 4 * AST_]);
                mma_tf32(o[nt], pa, vb);
            }
        }
        __syncthreads();   // all warps done with V/K/Ps before next kt's issues
    }
    #undef ISSUE_K
    #undef ISSUE_V

    // ---- finalize & store ----
    float inv[2] = { 1.0f / l[0], 1.0f / l[1] };
    float* Ob = g_Att + ((size_t)b * S_ + qt * 64) * D_ + h * 64;
    #pragma unroll
    for (int nt = 0; nt < 8; nt++)
        #pragma unroll
        for (int r = 0; r < 2; r++) {
            int row = w * 16 + g + 8 * r;
            int col = nt * 8 + 2 * tg;
            float2 ov = { o[nt][2 * r] * inv[r], o[nt][2 * r + 1] * inv[r] };
            *(float2*)(Ob + (size_t)row * D_ + col) = ov;
        }
}

// ---------------------------------------------------------------------------
extern "C" void kernel_launch(void* const* d_in, const int* in_sizes, int n_in,
                              void* d_out, int out_size)
{
    (void)in_sizes; (void)n_in; (void)out_size;
    const float* q  = (const float*)d_in[0];
    const float* k  = (const float*)d_in[1];
    const float* v  = (const float*)d_in[2];
    const float* Wq = (const float*)d_in[4];
    const float* bq = (const float*)d_in[5];
    const float* Wk = (const float*)d_in[6];
    const float* bk = (const float*)d_in[7];
    const float* Wv = (const float*)d_in[8];
    const float* bv = (const float*)d_in[9];
    const float* Wo = (const float*)d_in[10];
    const float* bo = (const float*)d_in[11];
    float* out = (float*)d_out;

    const int gemm_smem = 4 * GSTAGE_ * 4;           // 73728 B (2 stages)
    cudaFuncSetAttribute(qkv_gemm_mma, cudaFuncAttributeMaxDynamicSharedMemorySize, gemm_smem);
    cudaFuncSetAttribute(out_gemm_mma, cudaFuncAttributeMaxDynamicSharedMemorySize, gemm_smem);
    const int attn_smem = 4 * 64 * AST_ * 4;         // 69632 B -> 3 CTA/SM
    cudaFuncSetAttribute(attn_kernel, cudaFuncAttributeMaxDynamicSharedMemorySize, attn_smem);

    dim3 gqkv(1024/128, M_/128, 3);
    qkv_gemm_mma<<<gqkv, 256, gemm_smem>>>(q, k, v, Wq, bq, Wk, bk, Wv, bv);

    attn_kernel<<<dim3(S_/64, H_, B_), 128, attn_smem>>>();

    out_gemm_mma<<<dim3(1024/128, M_/128), 256, gemm_smem>>>(Wo, bo, out);
}

// round 12
// speedup vs baseline: 2.0422x; 1.0036x over previous
#include <cuda_runtime.h>
#include <math.h>
#include <stdint.h>

#define B_ 2
#define S_ 2048
#define D_ 1024
#define H_ 16
#define M_ (B_*S_)

// Scratch (allocation-free rule: __device__ globals)
__device__ float g_Qp[(size_t)B_*S_*D_];
__device__ float g_Kp[(size_t)B_*S_*D_];   // stored tf32-rounded
__device__ float g_Vp[(size_t)B_*S_*D_];   // stored tf32-rounded
__device__ float g_Att[(size_t)B_*S_*D_];

__device__ __forceinline__ uint32_t f2tf32(float x) {
    uint32_t r;
    asm("cvt.rna.tf32.f32 %0, %1;" : "=r"(r) : "f"(x));
    return r;
}

__device__ __forceinline__ void mma_tf32(float* d, const uint32_t* a, const uint32_t* b) {
    asm volatile(
        "mma.sync.aligned.m16n8k8.row.col.f32.tf32.tf32.f32 "
        "{%0,%1,%2,%3}, {%4,%5,%6,%7}, {%8,%9}, {%0,%1,%2,%3};"
        : "+f"(d[0]), "+f"(d[1]), "+f"(d[2]), "+f"(d[3])
        : "r"(a[0]), "r"(a[1]), "r"(a[2]), "r"(a[3]), "r"(b[0]), "r"(b[1]));
}

__device__ __forceinline__ uint32_t smem_u32(const void* p) {
    uint32_t a;
    asm("{ .reg .u64 t; cvta.to.shared.u64 t, %1; cvt.u32.u64 %0, t; }"
        : "=r"(a) : "l"(p));
    return a;
}

__device__ __forceinline__ void cp_async16(uint32_t saddr, const void* g) {
    asm volatile("cp.async.cg.shared.global [%0], [%1], 16;"
                 :: "r"(saddr), "l"(g) : "memory");
}
#define CP_COMMIT()  asm volatile("cp.async.commit_group;" ::: "memory")
#define CP_WAIT(n_)  asm volatile("cp.async.wait_group %0;" :: "n"(n_) : "memory")

// ---------------------------------------------------------------------------
// tf32 mma.sync GEMM (round-6 2-stage; best measured 198.0us on qkv)
// ROUND_TF32: round outputs to tf32 at store (for K/V consumed by attention;
// bit-identical to converting at attention fragment-load time).
// ---------------------------------------------------------------------------
#define GST_ 36
#define GSTAGE_ (128*GST_)

template<int DO_ROPE, int ROUND_TF32>
__device__ __forceinline__ void gemm_mma_body(const float* __restrict__ A,
                                              const float* __restrict__ W,
                                              const float* __restrict__ bias,
                                              float* __restrict__ C)
{
    extern __shared__ float gsm_[];
    float* Asf = gsm_;                    // [2][128][36]
    float* Bsf = gsm_ + 2 * GSTAGE_;      // [2][128][36]

    const int tid  = threadIdx.x;
    const int lane = tid & 31, w = tid >> 5;
    const int warpM = w & 1, warpN = w >> 1;
    const int g = lane >> 2, tg = lane & 3;
    const int m0 = blockIdx.y * 128, n0 = blockIdx.x * 128;

    const uint32_t sA_u = smem_u32(Asf);
    const uint32_t sB_u = smem_u32(Bsf);

    #define ISSUE_STAGE(s_, buf_) do {                                        \
        const int k0_ = (s_) * 32;                                            \
        _Pragma("unroll")                                                     \
        for (int t = 0; t < 4; t++) {                                         \
            int slot = tid + t * 256;                                         \
            int r = slot >> 3, qd = slot & 7;                                 \
            uint32_t so = (uint32_t)(((buf_) * GSTAGE_ + r * GST_ + qd * 4) * 4); \
            cp_async16(sA_u + so, A + (size_t)(m0 + r) * 1024 + k0_ + qd * 4);\
            cp_async16(sB_u + so, W + (size_t)(n0 + r) * 1024 + k0_ + qd * 4);\
        }                                                                     \
    } while (0)

    float acc[4][4][4];
    #pragma unroll
    for (int i = 0; i < 4; i++)
        #pragma unroll
        for (int j = 0; j < 4; j++)
            #pragma unroll
            for (int x = 0; x < 4; x++) acc[i][j][x] = 0.f;

    ISSUE_STAGE(0, 0);
    CP_COMMIT();

    #pragma unroll 1
    for (int s = 0; s < 32; s++) {
        if (s + 1 < 32) {
            ISSUE_STAGE(s + 1, (s + 1) & 1);
            CP_COMMIT();
            CP_WAIT(1);
        } else {
            CP_WAIT(0);
        }
        __syncthreads();

        const float* Ab = Asf + (s & 1) * GSTAGE_;
        const float* Bb = Bsf + (s & 1) * GSTAGE_;
        #pragma unroll
        for (int ks = 0; ks < 4; ks++) {
            const int kc = ks * 8 + tg;
            uint32_t af[4][4];
            #pragma unroll
            for (int mt = 0; mt < 4; mt++) {
                const float* p = Ab + (warpM * 64 + mt * 16 + g) * GST_ + kc;
                af[mt][0] = f2tf32(p[0]);
                af[mt][1] = f2tf32(p[8 * GST_]);
                af[mt][2] = f2tf32(p[4]);
                af[mt][3] = f2tf32(p[8 * GST_ + 4]);
            }
            uint32_t bf[4][2];
            #pragma unroll
            for (int nt = 0; nt < 4; nt++) {
                const float* p = Bb + (warpN * 8 + nt * 32 + g) * GST_ + kc;
                bf[nt][0] = f2tf32(p[0]);
                bf[nt][1] = f2tf32(p[4]);
            }
            #pragma unroll
            for (int mt = 0; mt < 4; mt++)
                #pragma unroll
                for (int nt = 0; nt < 4; nt++)
                    mma_tf32(acc[mt][nt], af[mt], bf[nt]);
        }
        __syncthreads();
    }
    #undef ISSUE_STAGE

    float bcol[4][2];
    #pragma unroll
    for (int nt = 0; nt < 4; nt++) {
        bcol[nt][0] = bias[n0 + warpN * 8 + nt * 32 + 2 * tg + 0];
        bcol[nt][1] = bias[n0 + warpN * 8 + nt * 32 + 2 * tg + 1];
    }
    #pragma unroll
    for (int mt = 0; mt < 4; mt++)
        #pragma unroll
        for (int nt = 0; nt < 4; nt++) {
            acc[mt][nt][0] += bcol[nt][0];
            acc[mt][nt][1] += bcol[nt][1];
            acc[mt][nt][2] += bcol[nt][0];
            acc[mt][nt][3] += bcol[nt][1];
        }

    if (DO_ROPE) {
        float sn[2][8], cs[2][8];
        #pragma unroll
        for (int jj = 0; jj < 2; jj++) {
            int jcol = warpN * 8 + 2 * tg + jj;
            float invf = (float)exp(-(double)jcol * 0.28782313662425574);
            #pragma unroll
            for (int mt = 0; mt < 4; mt++)
                #pragma unroll
                for (int half = 0; half < 2; half++) {
                    int row = m0 + warpM * 64 + mt * 16 + g + 8 * half;
                    float sp = (float)(row & (S_ - 1));
                    sincosf(sp * invf, &sn[jj][mt * 2 + half], &cs[jj][mt * 2 + half]);
                }
        }
        #pragma unroll
        for (int mt = 0; mt < 4; mt++)
            #pragma unroll
            for (int p = 0; p < 2; p++)
                #pragma unroll
                for (int idx = 0; idx < 4; idx++) {
                    int jj = idx & 1, half = idx >> 1;
                    float c = cs[jj][mt * 2 + half], s = sn[jj][mt * 2 + half];
                    float x1 = acc[mt][2 * p][idx], x2 = acc[mt][2 * p + 1][idx];
                    acc[mt][2 * p][idx]     = x1 * c - x2 * s;
                    acc[mt][2 * p + 1][idx] = x1 * s + x2 * c;
                }
    }

    #pragma unroll
    for (int mt = 0; mt < 4; mt++)
        #pragma unroll
        for (int nt = 0; nt < 4; nt++)
            #pragma unroll
            for (int half = 0; half < 2; half++) {
                int row = m0 + warpM * 64 + mt * 16 + g + 8 * half;
                int col = n0 + warpN * 8 + nt * 32 + 2 * tg;
                float2 ov;
                if (ROUND_TF32) {
                    ov.x = __uint_as_float(f2tf32(acc[mt][nt][half * 2]));
                    ov.y = __uint_as_float(f2tf32(acc[mt][nt][half * 2 + 1]));
                } else {
                    ov.x = acc[mt][nt][half * 2];
                    ov.y = acc[mt][nt][half * 2 + 1];
                }
                *(float2*)(C + (size_t)row * 1024 + col) = ov;
            }
}

__global__ __launch_bounds__(256, 2)
void qkv_gemm_mma(const float* __restrict__ q, const float* __restrict__ k,
                  const float* __restrict__ v,
                  const float* __restrict__ Wq, const float* __restrict__ bq,
                  const float* __restrict__ Wk, const float* __restrict__ bk,
                  const float* __restrict__ Wv, const float* __restrict__ bv)
{
    if (blockIdx.z == 0)      gemm_mma_body<1, 0>(q, Wq, bq, g_Qp);
    else if (blockIdx.z == 1) gemm_mma_body<1, 1>(k, Wk, bk, g_Kp);
    else                      gemm_mma_body<0, 1>(v, Wv, bv, g_Vp);
}

__global__ __launch_bounds__(256, 2)
void out_gemm_mma(const float* __restrict__ Wo, const float* __restrict__ bo,
                  float* __restrict__ out)
{
    gemm_mma_body<0, 0>(g_Att, Wo, bo, out);
}

// ---------------------------------------------------------------------------
// Causal flash attention v8: v7 structure; K/V arrive PRE-ROUNDED to tf32
// (rounded in the QKV GEMM epilogue), so the kt loop has ZERO cvt:
// fragments feed raw loaded bits straight to mma. Numerics bit-identical
// to round 11.
// smem = 4*64*68*4 = 69632 B -> 3 CTAs/SM.
// ---------------------------------------------------------------------------
#define AST_ 68
__global__ __launch_bounds__(128, 3) void attn_kernel()
{
    extern __shared__ float afm_[];
    float*    Kraw = afm_;                          // [2][64][68] (tf32 bits)
    float*    Vraw = afm_ + 2 * 64 * AST_;          // [64][68]    (tf32 bits)
    uint32_t* Ps   = (uint32_t*)(afm_ + 3 * 64 * AST_);

    const int tid = threadIdx.x;
    const int lane = tid & 31, w = tid >> 5;
    const int g = lane >> 2, tg = lane & 3;
    const int qt = (int)(gridDim.x - 1) - (int)blockIdx.x;   // heavy first
    const int h = blockIdx.y, b = blockIdx.z;

    const float* Qb = g_Qp + ((size_t)b * S_ + qt * 64) * D_ + h * 64;
    const float* Kb = g_Kp + (size_t)b * S_ * D_ + h * 64;
    const float* Vb = g_Vp + (size_t)b * S_ * D_ + h * 64;

    const uint32_t kraw_u = smem_u32(Kraw);
    const uint32_t vraw_u = smem_u32(Vraw);

    #define ISSUE_K(kt_, buf_) do {                                           \
        _Pragma("unroll")                                                     \
        for (int t = 0; t < 8; t++) {                                         \
            int slot = tid + t * 128;                                         \
            int r = slot >> 4, qd = slot & 15;                                \
            uint32_t so = (uint32_t)((((buf_) * 64 + r) * AST_ + qd * 4) * 4);\
            cp_async16(kraw_u + so, Kb + (size_t)((kt_) * 64 + r) * D_ + qd * 4); \
        }                                                                     \
    } while (0)
    #define ISSUE_V(kt_) do {                                                 \
        _Pragma("unroll")                                                     \
        for (int t = 0; t < 8; t++) {                                         \
            int slot = tid + t * 128;                                         \
            int r = slot >> 4, qd = slot & 15;                                \
            uint32_t so = (uint32_t)((r * AST_ + qd * 4) * 4);                \
            cp_async16(vraw_u + so, Vb + (size_t)((kt_) * 64 + r) * D_ + qd * 4); \
        }                                                                     \
    } while (0)

    ISSUE_K(0, 0); CP_COMMIT();

    // ---- Q a-fragments into registers (scaled 1/8, tf32, kt-invariant) ----
    uint32_t qf[8][4];
    {
        const float* q0 = Qb + (size_t)(w * 16 + g) * D_;
        const float* q1 = Qb + (size_t)(w * 16 + g + 8) * D_;
        #pragma unroll
        for (int ks = 0; ks < 8; ks++) {
            int c = ks * 8 + tg;
            qf[ks][0] = f2tf32(q0[c]     * 0.125f);
            qf[ks][1] = f2tf32(q1[c]     * 0.125f);
            qf[ks][2] = f2tf32(q0[c + 4] * 0.125f);
            qf[ks][3] = f2tf32(q1[c + 4] * 0.125f);
        }
    }

    float m[2], l[2], o[8][4];
    m[0] = m[1] = -INFINITY; l[0] = l[1] = 0.f;
    #pragma unroll
    for (int nt = 0; nt < 8; nt++)
        #pragma unroll
        for (int c = 0; c < 4; c++) o[nt][c] = 0.f;

    #pragma unroll 1
    for (int kt = 0; kt <= qt; kt++) {
        // prior end-of-loop sync guarantees Vraw/Ps/other-K-buf free
        ISSUE_V(kt); CP_COMMIT();
        if (kt + 1 <= qt) {
            ISSUE_K(kt + 1, (kt + 1) & 1); CP_COMMIT();
            CP_WAIT(2);               // K(kt) arrived; V(kt), K(kt+1) pending
        } else {
            CP_WAIT(1);               // K(kt) arrived; V(kt) pending
        }
        __syncthreads();

        const uint32_t* KtU = (const uint32_t*)(Kraw + (kt & 1) * 64 * AST_);

        // ---- S = Q K^T (1xTF32; K bits pre-rounded, no cvt) ----
        float sacc[8][4];
        #pragma unroll
        for (int nt = 0; nt < 8; nt++)
            #pragma unroll
            for (int c = 0; c < 4; c++) sacc[nt][c] = 0.f;

        #pragma unroll
        for (int ks = 0; ks < 8; ks++) {
            #pragma unroll
            for (int nt = 0; nt < 8; nt++) {
                const int bbase = (nt * 8 + g) * AST_ + ks * 8 + tg;
                uint32_t bh[2];
                bh[0] = KtU[bbase];
                bh[1] = KtU[bbase + 4];
                mma_tf32(sacc[nt], qf[ks], bh);
            }
        }

        // ---- masking (diag tile only) ----
        if (kt == qt) {
            #pragma unroll
            for (int nt = 0; nt < 8; nt++)
                #pragma unroll
                for (int c = 0; c < 4; c++) {
                    int colL = nt * 8 + 2 * tg + (c & 1);
                    int rowL = w * 16 + g + 8 * (c >> 1);
                    if (colL > rowL) sacc[nt][c] = -INFINITY;
                }
        }

        // ---- online softmax (rows g, g+8; stats replicated over tg quad) ----
        float rm[2] = {-INFINITY, -INFINITY};
        #pragma unroll
        for (int nt = 0; nt < 8; nt++) {
            rm[0] = fmaxf(rm[0], fmaxf(sacc[nt][0], sacc[nt][1]));
            rm[1] = fmaxf(rm[1], fmaxf(sacc[nt][2], sacc[nt][3]));
        }
        #pragma unroll
        for (int r = 0; r < 2; r++) {
            rm[r] = fmaxf(rm[r], __shfl_xor_sync(0xffffffffu, rm[r], 1));
            rm[r] = fmaxf(rm[r], __shfl_xor_sync(0xffffffffu, rm[r], 2));
        }
        float alpha[2], rs[2];
        #pragma unroll
        for (int r = 0; r < 2; r++) {
            float mn = fmaxf(m[r], rm[r]);
            alpha[r] = __expf(m[r] - mn);
            m[r] = mn;
            rs[r] = 0.f;
        }
        #pragma unroll
        for (int nt = 0; nt < 8; nt++) {
            #pragma unroll
            for (int c = 0; c < 4; c++) {
                int r = c >> 1;
                float p = __expf(sacc[nt][c] - m[r]);
                sacc[nt][c] = p;
                rs[r] += p;
            }
        }
        #pragma unroll
        for (int r = 0; r < 2; r++) {
            rs[r] += __shfl_xor_sync(0xffffffffu, rs[r], 1);
            rs[r] += __shfl_xor_sync(0xffffffffu, rs[r], 2);
            l[r] = l[r] * alpha[r] + rs[r];
        }
        #pragma unroll
        for (int nt = 0; nt < 8; nt++) {
            o[nt][0] *= alpha[0]; o[nt][1] *= alpha[0];
            o[nt][2] *= alpha[1]; o[nt][3] *= alpha[1];
        }

        // ---- store P^T [k][q] (warp-private columns) ----
        #pragma unroll
        for (int nt = 0; nt < 8; nt++)
            #pragma unroll
            for (int c = 0; c < 4; c++) {
                int kpos = nt * 8 + 2 * tg + (c & 1);
                int qrow = w * 16 + g + 8 * (c >> 1);
                Ps[kpos * AST_ + qrow] = f2tf32(sacc[nt][c]);
            }

        // ---- V must be resident now (was hidden behind S + softmax) ----
        if (kt + 1 <= qt) { CP_WAIT(1); } else { CP_WAIT(0); }
        __syncthreads();   // V + Ps visible to all warps

        // ---- O += P V (V bits pre-rounded, no cvt) ----
        const uint32_t* VtU = (const uint32_t*)Vraw;
        #pragma unroll
        for (int ks = 0; ks < 8; ks++) {
            const int pbase = (ks * 8 + tg) * AST_ + w * 16 + g;
            uint32_t pa[4];
            pa[0] = Ps[pbase];
            pa[1] = Ps[pbase + 8];
            pa[2] = Ps[pbase + 4 * AST_];
            pa[3] = Ps[pbase + 4 * AST_ + 8];
            #pragma unroll
            for (int nt = 0; nt < 8; nt++) {
                const int vbase = (ks * 8 + tg) * AST_ + nt * 8 + g;
                uint32_t vb[2];
                vb[0] = VtU[vbase];
                vb[1] = VtU[vbase + 4 * AST_];
                mma_tf32(o[nt], pa, vb);
            }
        }
        __syncthreads();   // all warps done with V/K/Ps before next kt's issues
    }
    #undef ISSUE_K
    #undef ISSUE_V

    // ---- finalize & store ----
    float inv[2] = { 1.0f / l[0], 1.0f / l[1] };
    float* Ob = g_Att + ((size_t)b * S_ + qt * 64) * D_ + h * 64;
    #pragma unroll
    for (int nt = 0; nt < 8; nt++)
        #pragma unroll
        for (int r = 0; r < 2; r++) {
            int row = w * 16 + g + 8 * r;
            int col = nt * 8 + 2 * tg;
            float2 ov = { o[nt][2 * r] * inv[r], o[nt][2 * r + 1] * inv[r] };
            *(float2*)(Ob + (size_t)row * D_ + col) = ov;
        }
}

// ---------------------------------------------------------------------------
extern "C" void kernel_launch(void* const* d_in, const int* in_sizes, int n_in,
                              void* d_out, int out_size)
{
    (void)in_sizes; (void)n_in; (void)out_size;
    const float* q  = (const float*)d_in[0];
    const float* k  = (const float*)d_in[1];
    const float* v  = (const float*)d_in[2];
    const float* Wq = (const float*)d_in[4];
    const float* bq = (const float*)d_in[5];
    const float* Wk = (const float*)d_in[6];
    const float* bk = (const float*)d_in[7];
    const float* Wv = (const float*)d_in[8];
    const float* bv = (const float*)d_in[9];
    const float* Wo = (const float*)d_in[10];
    const float* bo = (const float*)d_in[11];
    float* out = (float*)d_out;

    const int gemm_smem = 4 * GSTAGE_ * 4;           // 73728 B (2 stages)
    cudaFuncSetAttribute(qkv_gemm_mma, cudaFuncAttributeMaxDynamicSharedMemorySize, gemm_smem);
    cudaFuncSetAttribute(out_gemm_mma, cudaFuncAttributeMaxDynamicSharedMemorySize, gemm_smem);
    const int attn_smem = 4 * 64 * AST_ * 4;         // 69632 B -> 3 CTA/SM
    cudaFuncSetAttribute(attn_kernel, cudaFuncAttributeMaxDynamicSharedMemorySize, attn_smem);

    dim3 gqkv(1024/128, M_/128, 3);
    qkv_gemm_mma<<<gqkv, 256, gemm_smem>>>(q, k, v, Wq, bq, Wk, bk, Wv, bv);

    attn_kernel<<<dim3(S_/64, H_, B_), 128, attn_smem>>>();

    out_gemm_mma<<<dim3(1024/128, M_/128), 256, gemm_smem>>>(Wo, bo, out);
}